// round 4
// baseline (speedup 1.0000x reference)
#include <cuda_runtime.h>
#include <cuda_bf16.h>
#include <cstdint>

#define NPTS  60000
#define KNBR  27
#define CDIM  128
#define EPSBN 1e-5f
#define SLOPE 0.01f

// ---------------- device globals (no allocations allowed) ----------------
__device__ __align__(16) __nv_bfloat16 g_xhi[(size_t)NPTS * CDIM];
__device__ __align__(16) __nv_bfloat16 g_xlo[(size_t)NPTS * CDIM];
__device__ __align__(16) __nv_bfloat16 g_whi1[KNBR * CDIM * CDIM];  // [k][n][c] (transposed)
__device__ __align__(16) __nv_bfloat16 g_wlo1[KNBR * CDIM * CDIM];
__device__ __align__(16) __nv_bfloat16 g_whi2[KNBR * CDIM * CDIM];
__device__ __align__(16) __nv_bfloat16 g_wlo2[KNBR * CDIM * CDIM];
__device__ float         g_h1[(size_t)NPTS * CDIM];
__device__ unsigned char g_maskb[(size_t)NPTS * KNBR];
__device__ __align__(16) unsigned char g_zero[256];
__device__ float         g_sums[512];
__device__ float         g_bn[512];
__device__ unsigned      g_flags;
__device__ int           g_mask_mode;

// ---------------- mask dtype detection (validated R1) ----------------
__global__ void zero_kernel() {
    int t = threadIdx.x;
    if (t < 512) g_sums[t] = 0.f;
    if (t < 256) g_zero[t] = 0;
    if (t == 0)  g_flags = 0u;
}
__global__ void detect_kernel(const unsigned* __restrict__ w, int nwords) {
    unsigned f = 0u;
    for (int i = blockIdx.x * blockDim.x + threadIdx.x; i < nwords;
         i += gridDim.x * blockDim.x) {
        unsigned v = w[i];
        if (v == 0x3F800000u)                          f |= 1u;
        else if (v == 0x3F803F80u || v == 0x00003F80u) f |= 2u;
        else if (v > 1u)                               f |= 4u;
    }
    if (f) atomicOr(&g_flags, f);
}
__global__ void resolve_kernel() {
    unsigned f = g_flags;
    g_mask_mode = (f & 2u) ? 3 : (f & 1u) ? 0 : (f & 4u) ? 2 : 1;
}
__device__ __forceinline__ float load_mask(const void* m, long i, int mode) {
    switch (mode) {
        case 0:  return ((const float*)m)[i];
        case 1:  return (float)(((const int*)m)[i] != 0);
        case 2:  return (float)(((const unsigned char*)m)[i] != 0);
        default: return (((const unsigned short*)m)[i] != 0) ? 1.f : 0.f;
    }
}
__global__ void prep_mask_kernel(const void* __restrict__ mask) {
    long i = (long)blockIdx.x * blockDim.x + threadIdx.x;
    if (i < (long)NPTS * KNBR)
        g_maskb[i] = (load_mask(mask, i, g_mask_mode) != 0.f) ? 1 : 0;
}

// ---------------- fp32 -> bf16 hi/lo split ----------------
__device__ __forceinline__ void split2(float x, __nv_bfloat16& h, __nv_bfloat16& l) {
    h = __float2bfloat16_rn(x);
    l = __float2bfloat16_rn(x - __bfloat162float(h));
}
__global__ void prep_pack_kernel(const float* __restrict__ x) {
    long i = (long)blockIdx.x * blockDim.x + threadIdx.x;
    if (i < (long)NPTS * CDIM) {
        __nv_bfloat16 h, l; split2(x[i], h, l);
        g_xhi[i] = h; g_xlo[i] = l;
    }
}
__global__ void prep_w_kernel(const float* __restrict__ W,
                              __nv_bfloat16* __restrict__ Whi,
                              __nv_bfloat16* __restrict__ Wlo) {
    int i = blockIdx.x * blockDim.x + threadIdx.x;     // over 27*128*128, [k][n][c]
    if (i < KNBR * CDIM * CDIM) {
        int k = i >> 14, rem = i & 16383, n = rem >> 7, c = rem & 127;
        __nv_bfloat16 h, l; split2(W[(k << 14) + (c << 7) + n], h, l);
        Whi[i] = h; Wlo[i] = l;
    }
}

// ---------------- mma.sync gather-GEMM ----------------
#define STG      65536      // per-stage: A_hi 16K | A_lo 16K | B_hi 16K | B_lo 16K
#define OFF_AH   0
#define OFF_AL   16384
#define OFF_BH   32768
#define OFF_BL   49152
#define OFF_NBR  131072     // 128*27*4 = 13824
#define OFF_MSK  144896     // 128*27   = 3456
#define SMEM_DYN (148352 + 1024)
#define NSTAGES_TOTAL (2 * KNBR)   // 54

__device__ __forceinline__ uint32_t sw128(uint32_t off) { return off ^ ((off >> 3) & 0x70); }

__device__ __forceinline__ void cp16(uint32_t dst, const void* src) {
    asm volatile("cp.async.cg.shared.global [%0], [%1], 16;"
                 :: "r"(dst), "l"(src) : "memory");
}
#define CP_COMMIT() asm volatile("cp.async.commit_group;" ::: "memory")
#define CP_WAIT1()  asm volatile("cp.async.wait_group 1;" ::: "memory")

__device__ __forceinline__ void ldsm4(uint32_t* r, uint32_t addr) {
    asm volatile("ldmatrix.sync.aligned.m8n8.x4.shared.b16 {%0,%1,%2,%3}, [%4];"
                 : "=r"(r[0]), "=r"(r[1]), "=r"(r[2]), "=r"(r[3]) : "r"(addr));
}
__device__ __forceinline__ void mma16816(float* c, const uint32_t* a, const uint32_t* b) {
    asm volatile(
        "mma.sync.aligned.m16n8k16.row.col.f32.bf16.bf16.f32 "
        "{%0,%1,%2,%3}, {%4,%5,%6,%7}, {%8,%9}, {%0,%1,%2,%3};"
        : "+f"(c[0]), "+f"(c[1]), "+f"(c[2]), "+f"(c[3])
        : "r"(a[0]), "r"(a[1]), "r"(a[2]), "r"(a[3]), "r"(b[0]), "r"(b[1]));
}

__global__ __launch_bounds__(256, 1)
void conv_mma_kernel(const __nv_bfloat16* __restrict__ Xhi,
                     const __nv_bfloat16* __restrict__ Xlo,
                     const __nv_bfloat16* __restrict__ Whi,
                     const __nv_bfloat16* __restrict__ Wlo,
                     const int* __restrict__ nbr,
                     const unsigned char* __restrict__ maskb,
                     const unsigned char* __restrict__ zpage,
                     float* __restrict__ out)
{
    extern __shared__ char smem_raw[];
    uint32_t sb   = (uint32_t)__cvta_generic_to_shared(smem_raw);
    uint32_t base = (sb + 1023) & ~1023u;
    char* smem    = smem_raw + (base - sb);

    int*           s_nbr = (int*)(smem + OFF_NBR);
    unsigned char* s_msk = (unsigned char*)(smem + OFF_MSK);

    const int tid = threadIdx.x, lane = tid & 31, wid = tid >> 5;
    const int m0 = blockIdx.x * 128;

    for (int i = tid; i < 128 * KNBR; i += 256) {
        int r = i / KNBR, kk = i - r * KNBR, m = m0 + r;
        if (m < NPTS) { s_nbr[i] = nbr[(size_t)m * KNBR + kk]; s_msk[i] = maskb[(size_t)m * KNBR + kk]; }
        else          { s_nbr[i] = 0; s_msk[i] = 0; }
    }
    __syncthreads();

    float acc[2][8][4];
    #pragma unroll
    for (int mt = 0; mt < 2; ++mt)
        #pragma unroll
        for (int n = 0; n < 8; ++n)
            #pragma unroll
            for (int j = 0; j < 4; ++j) acc[mt][n][j] = 0.f;

    const int wm = (wid & 3) * 32;
    const int wn = (wid >> 2) * 64;

    // stage loader: stage s covers neighbor k=s>>1, channels cc..cc+63
    auto load_stage = [&](int s) {
        const int k = s >> 1, cc = (s & 1) << 6;
        const uint32_t stb = base + (uint32_t)(s & 1) * STG;
        #pragma unroll
        for (int j = 0; j < 4; ++j) {
            const int idx = tid * 4 + j;            // 0..1023
            const int row = idx >> 3, ch = idx & 7;
            const uint32_t woff = sw128((uint32_t)row * 128 + ch * 16);
            // A: gather (masked -> zero page)
            const int nb = s_nbr[row * KNBR + k];
            const bool mk = s_msk[row * KNBR + k] != 0;
            const size_t eoff = (size_t)nb * CDIM + cc + ch * 8;
            cp16(stb + OFF_AH + woff, mk ? (const void*)(Xhi + eoff) : (const void*)zpage);
            cp16(stb + OFF_AL + woff, mk ? (const void*)(Xlo + eoff) : (const void*)zpage);
            // B: W^T[k][row][cc + ch*8 ..]
            const size_t boff = ((size_t)k * CDIM + row) * CDIM + cc + ch * 8;
            cp16(stb + OFF_BH + woff, Whi + boff);
            cp16(stb + OFF_BL + woff, Wlo + boff);
        }
    };

    load_stage(0); CP_COMMIT();
    load_stage(1); CP_COMMIT();

    for (int s = 0; s < NSTAGES_TOTAL; ++s) {
        CP_WAIT1();
        __syncthreads();
        const uint32_t stb = base + (uint32_t)(s & 1) * STG;

        #pragma unroll
        for (int kk = 0; kk < 4; ++kk) {
            uint32_t aH[2][4], aL[2][4];
            #pragma unroll
            for (int mt = 0; mt < 2; ++mt) {
                const int row  = wm + mt * 16 + (lane & 7) + ((lane >> 3) & 1) * 8;
                const int colb = kk * 32 + ((lane >> 4) & 1) * 16;
                const uint32_t ad = stb + OFF_AH + sw128((uint32_t)row * 128 + colb);
                ldsm4(aH[mt], ad);
                ldsm4(aL[mt], ad + (OFF_AL - OFF_AH));
            }
            uint32_t bH[8][2], bL[8][2];
            #pragma unroll
            for (int nt = 0; nt < 4; ++nt) {
                const int nrow = wn + nt * 16 + ((lane >> 4) & 1) * 8 + (lane & 7);
                const int colb = kk * 32 + ((lane >> 3) & 1) * 16;
                const uint32_t bd = stb + OFF_BH + sw128((uint32_t)nrow * 128 + colb);
                uint32_t t[4];
                ldsm4(t, bd);
                bH[nt*2][0] = t[0]; bH[nt*2][1] = t[1]; bH[nt*2+1][0] = t[2]; bH[nt*2+1][1] = t[3];
                ldsm4(t, bd + (OFF_BL - OFF_BH));
                bL[nt*2][0] = t[0]; bL[nt*2][1] = t[1]; bL[nt*2+1][0] = t[2]; bL[nt*2+1][1] = t[3];
            }
            #pragma unroll
            for (int mt = 0; mt < 2; ++mt)
                #pragma unroll
                for (int n = 0; n < 8; ++n) {
                    mma16816(acc[mt][n], aH[mt], bH[n]);
                    mma16816(acc[mt][n], aH[mt], bL[n]);
                    mma16816(acc[mt][n], aL[mt], bH[n]);
                }
        }
        __syncthreads();
        if (s + 2 < NSTAGES_TOTAL) load_stage(s + 2);
        CP_COMMIT();
    }

    // epilogue: fp32 accumulators -> gmem
    #pragma unroll
    for (int mt = 0; mt < 2; ++mt) {
        const int row = m0 + wm + mt * 16 + (lane >> 2);
        #pragma unroll
        for (int n = 0; n < 8; ++n) {
            const int col = wn + n * 8 + (lane & 3) * 2;
            if (row < NPTS)
                *(float2*)(out + (size_t)row * CDIM + col) = make_float2(acc[mt][n][0], acc[mt][n][1]);
            if (row + 8 < NPTS)
                *(float2*)(out + (size_t)(row + 8) * CDIM + col) = make_float2(acc[mt][n][2], acc[mt][n][3]);
        }
    }
}

// ---------------- BN stats / finalize / fused elementwise ----------------
__global__ void stats_kernel(const float* __restrict__ h, int off) {
    int c = threadIdx.x;
    int row0 = blockIdx.x * 512;
    int rend = min(row0 + 512, NPTS);
    float s = 0.f, sq = 0.f;
    for (int r = row0; r < rend; ++r) {
        float v = h[(size_t)r * CDIM + c];
        s += v; sq += v * v;
    }
    atomicAdd(&g_sums[off + c], s);
    atomicAdd(&g_sums[off + 128 + c], sq);
}
__global__ void finalize_kernel(const float* __restrict__ gamma,
                                const float* __restrict__ beta, int off) {
    int c = threadIdx.x;
    const float invN = 1.f / (float)NPTS;
    float mean = g_sums[off + c] * invN;
    float var  = g_sums[off + 128 + c] * invN - mean * mean;
    float sc   = gamma[c] / sqrtf(var + EPSBN);
    g_bn[off + c]       = sc;
    g_bn[off + 128 + c] = beta[c] - mean * sc;
}
// y1 = lrelu(bn1(h1)) -> split bf16 hi/lo for conv2
__global__ void bn_lrelu_pack_kernel(const float* __restrict__ h) {
    int i = blockIdx.x * blockDim.x + threadIdx.x;
    if (i < NPTS * CDIM) {
        int c = i & 127;
        float v = fmaf(h[i], g_bn[c], g_bn[128 + c]);
        v = v > 0.f ? v : SLOPE * v;
        __nv_bfloat16 hh, ll; split2(v, hh, ll);
        g_xhi[i] = hh; g_xlo[i] = ll;
    }
}
// out = lrelu(bn2(h2) + x) in place
__global__ void bn_res_lrelu_kernel(float* __restrict__ h2, const float* __restrict__ x) {
    int i = blockIdx.x * blockDim.x + threadIdx.x;
    if (i < NPTS * CDIM) {
        int c = i & 127;
        float v = fmaf(h2[i], g_bn[256 + c], g_bn[384 + c]) + x[i];
        h2[i] = v > 0.f ? v : SLOPE * v;
    }
}

// ---------------- launch ----------------
extern "C" void kernel_launch(void* const* d_in, const int* in_sizes, int n_in,
                              void* d_out, int out_size)
{
    const float* x    = (const float*)d_in[0];
    const int*   nbr  = (const int*)d_in[1];
    const void*  mask = d_in[2];
    const float* W1   = (const float*)d_in[3];
    const float* W2   = (const float*)d_in[4];
    const float* g1   = (const float*)d_in[5];
    const float* b1   = (const float*)d_in[6];
    const float* g2   = (const float*)d_in[7];
    const float* b2   = (const float*)d_in[8];
    float* out = (float*)d_out;

    float* h1 = nullptr;           cudaGetSymbolAddress((void**)&h1, g_h1);
    __nv_bfloat16 *xhi, *xlo, *whi1, *wlo1, *whi2, *wlo2;
    cudaGetSymbolAddress((void**)&xhi,  g_xhi);
    cudaGetSymbolAddress((void**)&xlo,  g_xlo);
    cudaGetSymbolAddress((void**)&whi1, g_whi1);
    cudaGetSymbolAddress((void**)&wlo1, g_wlo1);
    cudaGetSymbolAddress((void**)&whi2, g_whi2);
    cudaGetSymbolAddress((void**)&wlo2, g_wlo2);
    unsigned char *mb, *zp;
    cudaGetSymbolAddress((void**)&mb, g_maskb);
    cudaGetSymbolAddress((void**)&zp, g_zero);

    cudaFuncSetAttribute(conv_mma_kernel,
                         cudaFuncAttributeMaxDynamicSharedMemorySize, SMEM_DYN);

    const int conv_blocks = (NPTS + 127) / 128;          // 469
    const int ew_blocks   = (NPTS * CDIM + 255) / 256;   // 30000
    const int st_blocks   = (NPTS + 511) / 512;          // 118
    const int w_blocks    = (KNBR * CDIM * CDIM + 255) / 256;
    const int mk_blocks   = (NPTS * KNBR + 255) / 256;
    const int mask_words  = (NPTS * KNBR) / 4;

    zero_kernel<<<1, 512>>>();
    detect_kernel<<<480, 256>>>((const unsigned*)mask, mask_words);
    resolve_kernel<<<1, 1>>>();
    prep_mask_kernel<<<mk_blocks, 256>>>(mask);
    prep_w_kernel<<<w_blocks, 256>>>(W1, whi1, wlo1);
    prep_w_kernel<<<w_blocks, 256>>>(W2, whi2, wlo2);
    prep_pack_kernel<<<ew_blocks, 256>>>(x);

    conv_mma_kernel<<<conv_blocks, 256, SMEM_DYN>>>(xhi, xlo, whi1, wlo1, nbr, mb, zp, h1);
    stats_kernel<<<st_blocks, 128>>>(h1, 0);
    finalize_kernel<<<1, 128>>>(g1, b1, 0);
    bn_lrelu_pack_kernel<<<ew_blocks, 256>>>(h1);

    conv_mma_kernel<<<conv_blocks, 256, SMEM_DYN>>>(xhi, xlo, whi2, wlo2, nbr, mb, zp, out);
    stats_kernel<<<st_blocks, 128>>>(out, 256);
    finalize_kernel<<<1, 128>>>(g2, b2, 256);
    bn_res_lrelu_kernel<<<ew_blocks, 256>>>(out, x);
}

// round 7
// speedup vs baseline: 2.1795x; 2.1795x over previous
#include <cuda_runtime.h>
#include <cuda_bf16.h>
#include <cstdint>

#define NPTS  60000
#define KNBR  27
#define CDIM  128
#define EPSBN 1e-5f
#define SLOPE 0.01f

// ---------------- device globals (no allocations allowed) ----------------
__device__ float    g_h1[(size_t)NPTS * CDIM];  // conv1 output / y1 scratch
__device__ float    g_sums[512];                // [0..255] conv1 sum/sumsq, [256..511] conv2
__device__ float    g_bn[512];                  // [off+c]=scale, [off+128+c]=shift
__device__ unsigned g_flags;
__device__ int      g_mask_mode;                // 0=f32, 1=i32, 2=u8/bool, 3=bf16

// ---------------- packed f32x2 helpers ----------------
__device__ __forceinline__ void fma2(unsigned long long& d,
                                     unsigned long long a, unsigned long long b) {
    asm("fma.rn.f32x2 %0, %1, %2, %0;" : "+l"(d) : "l"(a), "l"(b));
}
__device__ __forceinline__ unsigned long long pk2(float lo, float hi) {
    unsigned long long r;
    asm("mov.b64 %0, {%1, %2};" : "=l"(r) : "f"(lo), "f"(hi));
    return r;
}
__device__ __forceinline__ void upk2(unsigned long long v, float& lo, float& hi) {
    asm("mov.b64 {%0, %1}, %2;" : "=f"(lo), "=f"(hi) : "l"(v));
}

// ---------------- mask dtype detection (validated R1/R4) ----------------
__global__ void zero_kernel() {
    int t = threadIdx.x;
    if (t < 512) g_sums[t] = 0.f;
    if (t == 0)  g_flags = 0u;
}
__global__ void detect_kernel(const unsigned* __restrict__ w, int nwords) {
    unsigned f = 0u;
    for (int i = blockIdx.x * blockDim.x + threadIdx.x; i < nwords;
         i += gridDim.x * blockDim.x) {
        unsigned v = w[i];
        if (v == 0x3F800000u)                          f |= 1u;
        else if (v == 0x3F803F80u || v == 0x00003F80u) f |= 2u;
        else if (v > 1u)                               f |= 4u;
    }
    if (f) atomicOr(&g_flags, f);
}
__global__ void resolve_kernel() {
    unsigned f = g_flags;
    g_mask_mode = (f & 2u) ? 3 : (f & 1u) ? 0 : (f & 4u) ? 2 : 1;
}
__device__ __forceinline__ float load_mask(const void* m, long i, int mode) {
    switch (mode) {
        case 0:  return ((const float*)m)[i];
        case 1:  return (float)(((const int*)m)[i] != 0);
        case 2:  return (float)(((const unsigned char*)m)[i] != 0);
        default: return (((const unsigned short*)m)[i] != 0) ? 1.f : 0.f;
    }
}

// ---------------- gather-GEMM with packed fma.rn.f32x2 ----------------
// out[m,:] = sum_k mask[m,k]*x[nbr[m,k],:] @ W[k];  tile 128x128, K-chunks of 16.
__global__ __launch_bounds__(256, 2)
void conv_gemm_kernel(const float* __restrict__ X, const int* __restrict__ nbr,
                      const void* __restrict__ mask, const float* __restrict__ W,
                      float* __restrict__ out)
{
    __shared__ float As[16][132];           // A^T: As[ck][m], padded
    __shared__ float Bs[16][128];
    __shared__ int   s_nbr[128 * KNBR];
    __shared__ float s_msk[128 * KNBR];

    const int tid = threadIdx.x;
    const int tx  = tid & 15;
    const int ty  = tid >> 4;
    const int m0  = blockIdx.x * 128;
    const int mode = g_mask_mode;

    // preload all neighbor ids + masks for this tile (once)
    for (int i = tid; i < 128 * KNBR; i += 256) {
        int r = i / KNBR, kk = i - r * KNBR, m = m0 + r;
        if (m < NPTS) {
            long idx = (long)m * KNBR + kk;
            s_nbr[i] = nbr[idx];
            s_msk[i] = load_mask(mask, idx, mode);
        } else { s_nbr[i] = 0; s_msk[i] = 0.f; }
    }
    __syncthreads();

    // packed accumulators: acc2[i4][j] = (C[ty*8+2*i4][tx*8+j], C[ty*8+2*i4+1][tx*8+j])
    unsigned long long acc2[4][8];
    #pragma unroll
    for (int i = 0; i < 4; ++i)
        #pragma unroll
        for (int j = 0; j < 8; ++j) acc2[i][j] = 0ULL;

    const int q    = tid & 3;
    const int mrow = tid >> 2;
    const int r0   = tid >> 5;
    const int cl   = (tid & 31) * 4;

    for (int k = 0; k < KNBR; ++k) {
        const float* wp = W + (size_t)k * CDIM * CDIM;
        for (int cc = 0; cc < CDIM; cc += 16) {
            // ---- gather A tile: 128 rows x 16 channels, mask folded ----
            #pragma unroll
            for (int p = 0; p < 2; ++p) {
                int m = mrow + p * 64;
                const float4 v = *reinterpret_cast<const float4*>(
                    X + (size_t)s_nbr[m * KNBR + k] * CDIM + cc + q * 4);
                float mk = s_msk[m * KNBR + k];
                As[q * 4 + 0][m] = v.x * mk;
                As[q * 4 + 1][m] = v.y * mk;
                As[q * 4 + 2][m] = v.z * mk;
                As[q * 4 + 3][m] = v.w * mk;
            }
            // ---- load B tile: W[k][cc:cc+16][0:128] ----
            #pragma unroll
            for (int p = 0; p < 2; ++p) {
                int r = r0 + p * 8;
                *reinterpret_cast<float4*>(&Bs[r][cl]) =
                    *reinterpret_cast<const float4*>(wp + (size_t)(cc + r) * CDIM + cl);
            }
            __syncthreads();

            #pragma unroll
            for (int ck = 0; ck < 16; ++ck) {
                // a rows as packed pairs (16B-aligned: row stride 132*4=528B, ty*8*4=32B)
                const ulonglong2 aA = *reinterpret_cast<const ulonglong2*>(&As[ck][ty * 8]);
                const ulonglong2 aB = *reinterpret_cast<const ulonglong2*>(&As[ck][ty * 8 + 4]);
                const unsigned long long a2[4] = { aA.x, aA.y, aB.x, aB.y };
                const float4 b0 = *reinterpret_cast<const float4*>(&Bs[ck][tx * 8]);
                const float4 b1 = *reinterpret_cast<const float4*>(&Bs[ck][tx * 8 + 4]);
                unsigned long long bp[8];
                bp[0] = pk2(b0.x, b0.x); bp[1] = pk2(b0.y, b0.y);
                bp[2] = pk2(b0.z, b0.z); bp[3] = pk2(b0.w, b0.w);
                bp[4] = pk2(b1.x, b1.x); bp[5] = pk2(b1.y, b1.y);
                bp[6] = pk2(b1.z, b1.z); bp[7] = pk2(b1.w, b1.w);
                #pragma unroll
                for (int i = 0; i < 4; ++i)
                    #pragma unroll
                    for (int j = 0; j < 8; ++j)
                        fma2(acc2[i][j], a2[i], bp[j]);
            }
            __syncthreads();
        }
    }

    // epilogue: unpack packed pairs -> rows (ty*8+2*i4, ty*8+2*i4+1)
    #pragma unroll
    for (int i4 = 0; i4 < 4; ++i4) {
        float o0[8], o1[8];
        #pragma unroll
        for (int j = 0; j < 8; ++j) upk2(acc2[i4][j], o0[j], o1[j]);
        int mA = m0 + ty * 8 + 2 * i4;
        int mB = mA + 1;
        if (mA < NPTS) {
            *reinterpret_cast<float4*>(out + (size_t)mA * CDIM + tx * 8)     = make_float4(o0[0], o0[1], o0[2], o0[3]);
            *reinterpret_cast<float4*>(out + (size_t)mA * CDIM + tx * 8 + 4) = make_float4(o0[4], o0[5], o0[6], o0[7]);
        }
        if (mB < NPTS) {
            *reinterpret_cast<float4*>(out + (size_t)mB * CDIM + tx * 8)     = make_float4(o1[0], o1[1], o1[2], o1[3]);
            *reinterpret_cast<float4*>(out + (size_t)mB * CDIM + tx * 8 + 4) = make_float4(o1[4], o1[5], o1[6], o1[7]);
        }
    }
}

// ---------------- BN stats / finalize / fused elementwise ----------------
__global__ void stats_kernel(const float* __restrict__ h, int off) {
    int c    = threadIdx.x;
    int row0 = blockIdx.x * 512;
    int rend = min(row0 + 512, NPTS);
    float s = 0.f, sq = 0.f;
    for (int r = row0; r < rend; ++r) {
        float v = h[(size_t)r * CDIM + c];
        s += v; sq += v * v;
    }
    atomicAdd(&g_sums[off + c], s);
    atomicAdd(&g_sums[off + 128 + c], sq);
}
__global__ void finalize_kernel(const float* __restrict__ gamma,
                                const float* __restrict__ beta, int off) {
    int c = threadIdx.x;
    const float invN = 1.f / (float)NPTS;
    float mean = g_sums[off + c] * invN;
    float var  = g_sums[off + 128 + c] * invN - mean * mean;
    float sc   = gamma[c] / sqrtf(var + EPSBN);
    g_bn[off + c]       = sc;
    g_bn[off + 128 + c] = beta[c] - mean * sc;
}
__global__ void bn_lrelu_kernel(float* __restrict__ h) {
    int i = blockIdx.x * blockDim.x + threadIdx.x;
    if (i < NPTS * CDIM) {
        int c = i & 127;
        float v = fmaf(h[i], g_bn[c], g_bn[128 + c]);
        h[i] = v > 0.f ? v : SLOPE * v;
    }
}
__global__ void bn_res_lrelu_kernel(float* __restrict__ h2, const float* __restrict__ x) {
    int i = blockIdx.x * blockDim.x + threadIdx.x;
    if (i < NPTS * CDIM) {
        int c = i & 127;
        float v = fmaf(h2[i], g_bn[256 + c], g_bn[384 + c]) + x[i];
        h2[i] = v > 0.f ? v : SLOPE * v;
    }
}

// ---------------- launch ----------------
extern "C" void kernel_launch(void* const* d_in, const int* in_sizes, int n_in,
                              void* d_out, int out_size)
{
    const float* x    = (const float*)d_in[0];
    const int*   nbr  = (const int*)d_in[1];
    const void*  mask = d_in[2];
    const float* W1   = (const float*)d_in[3];
    const float* W2   = (const float*)d_in[4];
    const float* g1   = (const float*)d_in[5];
    const float* b1   = (const float*)d_in[6];
    const float* g2   = (const float*)d_in[7];
    const float* b2   = (const float*)d_in[8];
    float* out = (float*)d_out;

    float* h1 = nullptr;
    cudaGetSymbolAddress((void**)&h1, g_h1);

    const int conv_blocks = (NPTS + 127) / 128;        // 469
    const int ew_blocks   = (NPTS * CDIM + 255) / 256; // 30000
    const int st_blocks   = (NPTS + 511) / 512;        // 118
    const int mask_words  = (NPTS * KNBR) / 4;         // 405000

    zero_kernel<<<1, 512>>>();
    detect_kernel<<<480, 256>>>((const unsigned*)mask, mask_words);
    resolve_kernel<<<1, 1>>>();

    conv_gemm_kernel<<<conv_blocks, 256>>>(x, nbr, mask, W1, h1);
    stats_kernel<<<st_blocks, 128>>>(h1, 0);
    finalize_kernel<<<1, 128>>>(g1, b1, 0);
    bn_lrelu_kernel<<<ew_blocks, 256>>>(h1);

    conv_gemm_kernel<<<conv_blocks, 256>>>(h1, nbr, mask, W2, out);
    stats_kernel<<<st_blocks, 128>>>(out, 256);
    finalize_kernel<<<1, 128>>>(g2, b2, 256);
    bn_res_lrelu_kernel<<<ew_blocks, 256>>>(out, x);
}